// round 2
// baseline (speedup 1.0000x reference)
#include <cuda_runtime.h>
#include <cstdint>

#define NN 1000000
#define NE 16000000

// ---- scratch (device globals; no allocations allowed) ----
__device__ int    g_deg[NN];
__device__ float  g_dis[NN];
__device__ float  g_u[NN];
__device__ float  g_acc1[NN];
__device__ float2 g_t[NN];
__device__ float2 g_acc2[NN];

// ---- no-return global reductions ----
__device__ __forceinline__ void red_add_u32(int* addr) {
    asm volatile("red.global.add.u32 [%0], 1;" :: "l"(addr) : "memory");
}
__device__ __forceinline__ void red_add_f32(float* addr, float v) {
    asm volatile("red.global.add.f32 [%0], %1;" :: "l"(addr), "f"(v) : "memory");
}
__device__ __forceinline__ void red_add_v2(float2* addr, float2 v) {
    asm volatile("red.global.add.v2.f32 [%0], {%1, %2};"
                 :: "l"(addr), "f"(v.x), "f"(v.y) : "memory");
}

// ---------------------------------------------------------------------------
// zero scratch accumulators (deg=0; self-loop folded into k_prep as deg+1)
__global__ __launch_bounds__(256) void k_zero() {
    int i = blockIdx.x * blockDim.x + threadIdx.x;
    if (i < NN) {
        g_deg[i]  = 0;
        g_acc1[i] = 0.0f;
        g_acc2[i] = make_float2(0.0f, 0.0f);
    }
}

// degree count over target (col) indices; 8 edges per thread
__global__ __launch_bounds__(256) void k_deg(const int* __restrict__ col, int E) {
    long long i = (long long)(blockIdx.x * blockDim.x + threadIdx.x) * 8;
    if (i + 7 < E) {
        int4 a = __ldcs(reinterpret_cast<const int4*>(col + i));
        int4 b = __ldcs(reinterpret_cast<const int4*>(col + i + 4));
        red_add_u32(&g_deg[a.x]);
        red_add_u32(&g_deg[a.y]);
        red_add_u32(&g_deg[a.z]);
        red_add_u32(&g_deg[a.w]);
        red_add_u32(&g_deg[b.x]);
        red_add_u32(&g_deg[b.y]);
        red_add_u32(&g_deg[b.z]);
        red_add_u32(&g_deg[b.w]);
    }
}

// dis = rsqrt(deg + 1 self-loop); u = dis * x
__global__ __launch_bounds__(256) void k_prep(const float* __restrict__ x) {
    int i = blockIdx.x * blockDim.x + threadIdx.x;
    if (i < NN) {
        float d = rsqrtf((float)(g_deg[i] + 1));
        g_dis[i] = d;
        g_u[i]   = d * x[i];
    }
}

// scatter layer-1 messages: acc1[col] += u[row]; 8 edges per thread
__global__ __launch_bounds__(256) void k_scat1(const int* __restrict__ row,
                                               const int* __restrict__ col, int E) {
    long long i = (long long)(blockIdx.x * blockDim.x + threadIdx.x) * 8;
    if (i + 7 < E) {
        int4 ra = __ldcs(reinterpret_cast<const int4*>(row + i));
        int4 rb = __ldcs(reinterpret_cast<const int4*>(row + i + 4));
        int4 ca = __ldcs(reinterpret_cast<const int4*>(col + i));
        int4 cb = __ldcs(reinterpret_cast<const int4*>(col + i + 4));
        float u0 = __ldg(&g_u[ra.x]);
        float u1 = __ldg(&g_u[ra.y]);
        float u2 = __ldg(&g_u[ra.z]);
        float u3 = __ldg(&g_u[ra.w]);
        float u4 = __ldg(&g_u[rb.x]);
        float u5 = __ldg(&g_u[rb.y]);
        float u6 = __ldg(&g_u[rb.z]);
        float u7 = __ldg(&g_u[rb.w]);
        red_add_f32(&g_acc1[ca.x], u0);
        red_add_f32(&g_acc1[ca.y], u1);
        red_add_f32(&g_acc1[ca.z], u2);
        red_add_f32(&g_acc1[ca.w], u3);
        red_add_f32(&g_acc1[cb.x], u4);
        red_add_f32(&g_acc1[cb.y], u5);
        red_add_f32(&g_acc1[cb.z], u6);
        red_add_f32(&g_acc1[cb.w], u7);
    }
}

// per-node MLP: s -> relu(W1*s+b1) -> @W2 ; t = dis * g
__global__ __launch_bounds__(256) void k_node2(const float4* __restrict__ W1,
                                               const float4* __restrict__ b1,
                                               const float4* __restrict__ W2) {
    int i = blockIdx.x * blockDim.x + threadIdx.x;
    if (i >= NN) return;
    float d = g_dis[i];
    float s = d * (g_acc1[i] + g_u[i]);
    float g0 = 0.0f, g1 = 0.0f;
#pragma unroll
    for (int q = 0; q < 4; q++) {
        float4 w1 = __ldg(&W1[q]);
        float4 bb = __ldg(&b1[q]);
        float4 e0 = __ldg(&W2[2 * q]);       // (k0c0,k0c1,k1c0,k1c1)
        float4 e1 = __ldg(&W2[2 * q + 1]);   // (k2c0,k2c1,k3c0,k3c1)
        float h0 = fmaxf(fmaf(s, w1.x, bb.x), 0.0f);
        float h1 = fmaxf(fmaf(s, w1.y, bb.y), 0.0f);
        float h2 = fmaxf(fmaf(s, w1.z, bb.z), 0.0f);
        float h3 = fmaxf(fmaf(s, w1.w, bb.w), 0.0f);
        g0 = fmaf(h0, e0.x, g0); g1 = fmaf(h0, e0.y, g1);
        g0 = fmaf(h1, e0.z, g0); g1 = fmaf(h1, e0.w, g1);
        g0 = fmaf(h2, e1.x, g0); g1 = fmaf(h2, e1.y, g1);
        g0 = fmaf(h3, e1.z, g0); g1 = fmaf(h3, e1.w, g1);
    }
    g_t[i] = make_float2(d * g0, d * g1);
}

// scatter layer-2 messages: acc2[col] += t[row]; 8 edges per thread
__global__ __launch_bounds__(256) void k_scat2(const int* __restrict__ row,
                                               const int* __restrict__ col, int E) {
    long long i = (long long)(blockIdx.x * blockDim.x + threadIdx.x) * 8;
    if (i + 7 < E) {
        int4 ra = __ldcs(reinterpret_cast<const int4*>(row + i));
        int4 rb = __ldcs(reinterpret_cast<const int4*>(row + i + 4));
        int4 ca = __ldcs(reinterpret_cast<const int4*>(col + i));
        int4 cb = __ldcs(reinterpret_cast<const int4*>(col + i + 4));
        float2 t0 = __ldg(&g_t[ra.x]);
        float2 t1 = __ldg(&g_t[ra.y]);
        float2 t2 = __ldg(&g_t[ra.z]);
        float2 t3 = __ldg(&g_t[ra.w]);
        float2 t4 = __ldg(&g_t[rb.x]);
        float2 t5 = __ldg(&g_t[rb.y]);
        float2 t6 = __ldg(&g_t[rb.z]);
        float2 t7 = __ldg(&g_t[rb.w]);
        red_add_v2(&g_acc2[ca.x], t0);
        red_add_v2(&g_acc2[ca.y], t1);
        red_add_v2(&g_acc2[ca.z], t2);
        red_add_v2(&g_acc2[ca.w], t3);
        red_add_v2(&g_acc2[cb.x], t4);
        red_add_v2(&g_acc2[cb.y], t5);
        red_add_v2(&g_acc2[cb.z], t6);
        red_add_v2(&g_acc2[cb.w], t7);
    }
}

// final: out = dis*(acc2 + t) + b2, then log_softmax over 2 classes
__global__ __launch_bounds__(256) void k_out(const float* __restrict__ b2,
                                             float2* __restrict__ out) {
    int i = blockIdx.x * blockDim.x + threadIdx.x;
    if (i >= NN) return;
    float d  = g_dis[i];
    float2 a = g_acc2[i];
    float2 t = g_t[i];
    float b20 = __ldg(&b2[0]);
    float b21 = __ldg(&b2[1]);
    float o0 = fmaf(d, a.x + t.x, b20);
    float o1 = fmaf(d, a.y + t.y, b21);
    float m  = fmaxf(o0, o1);
    float lse = m + log1pf(__expf(fminf(o0, o1) - m));
    out[i] = make_float2(o0 - lse, o1 - lse);
}

// ---------------------------------------------------------------------------
extern "C" void kernel_launch(void* const* d_in, const int* in_sizes, int n_in,
                              void* d_out, int out_size) {
    const float* x   = (const float*)d_in[0];
    const int*   ei  = (const int*)d_in[1];
    const float* b1  = (const float*)d_in[3];
    const float* W1  = (const float*)d_in[2];
    const float* W2  = (const float*)d_in[4];
    const float* b2  = (const float*)d_in[5];
    float2* out = (float2*)d_out;

    const int E = in_sizes[1] / 2;      // edge_index is [2, E]
    const int* row = ei;                // source
    const int* col = ei + E;            // target

    const int TB = 256;
    const int nodeBlocks = (NN + TB - 1) / TB;
    const int edgeBlocks = (E / 8 + TB - 1) / TB;   // 8 edges per thread

    k_zero <<<nodeBlocks, TB>>>();
    k_deg  <<<edgeBlocks, TB>>>(col, E);
    k_prep <<<nodeBlocks, TB>>>(x);
    k_scat1<<<edgeBlocks, TB>>>(row, col, E);
    k_node2<<<nodeBlocks, TB>>>((const float4*)W1, (const float4*)b1,
                                (const float4*)W2);
    k_scat2<<<edgeBlocks, TB>>>(row, col, E);
    k_out  <<<nodeBlocks, TB>>>(b2, out);
}

// round 3
// speedup vs baseline: 1.0120x; 1.0120x over previous
#include <cuda_runtime.h>
#include <cstdint>

#define NN 1000000
#define NE 16000000

// ---- scratch (device globals; no allocations allowed) ----
__device__ int    g_deg[NN];
__device__ float  g_dis[NN];
__device__ float  g_u[NN];
__device__ float  g_acc1[NN];
__device__ float2 g_t[NN];
__device__ float2 g_acc2[NN];

// ---- no-return global reductions ----
__device__ __forceinline__ void red_add_u32(int* addr) {
    asm volatile("red.global.add.u32 [%0], 1;" :: "l"(addr) : "memory");
}
__device__ __forceinline__ void red_add_f32(float* addr, float v) {
    asm volatile("red.global.add.f32 [%0], %1;" :: "l"(addr), "f"(v) : "memory");
}
__device__ __forceinline__ void red_add_v2(float2* addr, float2 v) {
    asm volatile("red.global.add.v2.f32 [%0], {%1, %2};"
                 :: "l"(addr), "f"(v.x), "f"(v.y) : "memory");
}

// ---------------------------------------------------------------------------
// zero ONLY the degree array (acc zeroing folded into k_prep / k_node2)
__global__ __launch_bounds__(256) void k_zero() {
    int i = blockIdx.x * blockDim.x + threadIdx.x;
    if (i < NN) g_deg[i] = 0;
}

// degree count over target (col) indices; 4 edges per thread
__global__ __launch_bounds__(256) void k_deg(const int* __restrict__ col, int E) {
    int i = (blockIdx.x * blockDim.x + threadIdx.x) * 4;
    if (i + 3 < E) {
        int4 c = __ldcs(reinterpret_cast<const int4*>(col + i));
        red_add_u32(&g_deg[c.x]);
        red_add_u32(&g_deg[c.y]);
        red_add_u32(&g_deg[c.z]);
        red_add_u32(&g_deg[c.w]);
    }
}

// dis = rsqrt(deg + 1 self-loop); u = dis * x; also zero acc1 for k_scat1
__global__ __launch_bounds__(256) void k_prep(const float* __restrict__ x) {
    int i = blockIdx.x * blockDim.x + threadIdx.x;
    if (i < NN) {
        float d = rsqrtf((float)(g_deg[i] + 1));
        g_dis[i]  = d;
        g_u[i]    = d * x[i];
        g_acc1[i] = 0.0f;
    }
}

// scatter layer-1 messages: acc1[col] += u[row]; 4 edges per thread
__global__ __launch_bounds__(256) void k_scat1(const int* __restrict__ row,
                                               const int* __restrict__ col, int E) {
    int i = (blockIdx.x * blockDim.x + threadIdx.x) * 4;
    if (i + 3 < E) {
        int4 r = __ldcs(reinterpret_cast<const int4*>(row + i));
        int4 c = __ldcs(reinterpret_cast<const int4*>(col + i));
        float u0 = __ldg(&g_u[r.x]);
        float u1 = __ldg(&g_u[r.y]);
        float u2 = __ldg(&g_u[r.z]);
        float u3 = __ldg(&g_u[r.w]);
        red_add_f32(&g_acc1[c.x], u0);
        red_add_f32(&g_acc1[c.y], u1);
        red_add_f32(&g_acc1[c.z], u2);
        red_add_f32(&g_acc1[c.w], u3);
    }
}

// per-node MLP: s -> relu(W1*s+b1) -> @W2 ; t = dis * g; also zero acc2
__global__ __launch_bounds__(256) void k_node2(const float4* __restrict__ W1,
                                               const float4* __restrict__ b1,
                                               const float4* __restrict__ W2) {
    int i = blockIdx.x * blockDim.x + threadIdx.x;
    if (i >= NN) return;
    float d = g_dis[i];
    float s = d * (g_acc1[i] + g_u[i]);
    float g0 = 0.0f, g1 = 0.0f;
#pragma unroll
    for (int q = 0; q < 4; q++) {
        float4 w1 = __ldg(&W1[q]);
        float4 bb = __ldg(&b1[q]);
        float4 e0 = __ldg(&W2[2 * q]);       // (k0c0,k0c1,k1c0,k1c1)
        float4 e1 = __ldg(&W2[2 * q + 1]);   // (k2c0,k2c1,k3c0,k3c1)
        float h0 = fmaxf(fmaf(s, w1.x, bb.x), 0.0f);
        float h1 = fmaxf(fmaf(s, w1.y, bb.y), 0.0f);
        float h2 = fmaxf(fmaf(s, w1.z, bb.z), 0.0f);
        float h3 = fmaxf(fmaf(s, w1.w, bb.w), 0.0f);
        g0 = fmaf(h0, e0.x, g0); g1 = fmaf(h0, e0.y, g1);
        g0 = fmaf(h1, e0.z, g0); g1 = fmaf(h1, e0.w, g1);
        g0 = fmaf(h2, e1.x, g0); g1 = fmaf(h2, e1.y, g1);
        g0 = fmaf(h3, e1.z, g0); g1 = fmaf(h3, e1.w, g1);
    }
    g_t[i]    = make_float2(d * g0, d * g1);
    g_acc2[i] = make_float2(0.0f, 0.0f);
}

// scatter layer-2 messages: acc2[col] += t[row]; 4 edges per thread
__global__ __launch_bounds__(256) void k_scat2(const int* __restrict__ row,
                                               const int* __restrict__ col, int E) {
    int i = (blockIdx.x * blockDim.x + threadIdx.x) * 4;
    if (i + 3 < E) {
        int4 r = __ldcs(reinterpret_cast<const int4*>(row + i));
        int4 c = __ldcs(reinterpret_cast<const int4*>(col + i));
        float2 t0 = __ldg(&g_t[r.x]);
        float2 t1 = __ldg(&g_t[r.y]);
        float2 t2 = __ldg(&g_t[r.z]);
        float2 t3 = __ldg(&g_t[r.w]);
        red_add_v2(&g_acc2[c.x], t0);
        red_add_v2(&g_acc2[c.y], t1);
        red_add_v2(&g_acc2[c.z], t2);
        red_add_v2(&g_acc2[c.w], t3);
    }
}

// final: out = dis*(acc2 + t) + b2, then log_softmax over 2 classes
__global__ __launch_bounds__(256) void k_out(const float* __restrict__ b2,
                                             float2* __restrict__ out) {
    int i = blockIdx.x * blockDim.x + threadIdx.x;
    if (i >= NN) return;
    float d  = g_dis[i];
    float2 a = g_acc2[i];
    float2 t = g_t[i];
    float b20 = __ldg(&b2[0]);
    float b21 = __ldg(&b2[1]);
    float o0 = fmaf(d, a.x + t.x, b20);
    float o1 = fmaf(d, a.y + t.y, b21);
    float m  = fmaxf(o0, o1);
    float lse = m + log1pf(__expf(fminf(o0, o1) - m));
    out[i] = make_float2(o0 - lse, o1 - lse);
}

// ---------------------------------------------------------------------------
extern "C" void kernel_launch(void* const* d_in, const int* in_sizes, int n_in,
                              void* d_out, int out_size) {
    const float* x   = (const float*)d_in[0];
    const int*   ei  = (const int*)d_in[1];
    const float* W1  = (const float*)d_in[2];
    const float* b1  = (const float*)d_in[3];
    const float* W2  = (const float*)d_in[4];
    const float* b2  = (const float*)d_in[5];
    float2* out = (float2*)d_out;

    const int E = in_sizes[1] / 2;      // edge_index is [2, E]
    const int* row = ei;                // source
    const int* col = ei + E;            // target

    const int TB = 256;
    const int nodeBlocks = (NN + TB - 1) / TB;
    const int edgeBlocks = (E / 4 + TB - 1) / TB;   // 4 edges per thread

    k_zero <<<nodeBlocks, TB>>>();
    k_deg  <<<edgeBlocks, TB>>>(col, E);
    k_prep <<<nodeBlocks, TB>>>(x);
    k_scat1<<<edgeBlocks, TB>>>(row, col, E);
    k_node2<<<nodeBlocks, TB>>>((const float4*)W1, (const float4*)b1,
                                (const float4*)W2);
    k_scat2<<<edgeBlocks, TB>>>(row, col, E);
    k_out  <<<nodeBlocks, TB>>>(b2, out);
}

// round 4
// speedup vs baseline: 1.0128x; 1.0009x over previous
#include <cuda_runtime.h>
#include <cstdint>

#define NN 1000000
#define NE 16000000

// ---- scratch (device globals; no allocations allowed) ----
__device__ int    g_deg[NN];
__device__ float  g_dis[NN];
__device__ float  g_u[NN];
__device__ float  g_acc1[NN];
__device__ float2 g_t[NN];
__device__ float2 g_acc2[NN];

// ---- no-return global reductions ----
__device__ __forceinline__ void red_add_u32(int* addr) {
    asm volatile("red.global.add.u32 [%0], 1;" :: "l"(addr) : "memory");
}
__device__ __forceinline__ void red_add_f32(float* addr, float v) {
    asm volatile("red.global.add.f32 [%0], %1;" :: "l"(addr), "f"(v) : "memory");
}
__device__ __forceinline__ void red_add_v2(float2* addr, float2 v) {
    asm volatile("red.global.add.v2.f32 [%0], {%1, %2};"
                 :: "l"(addr), "f"(v.x), "f"(v.y) : "memory");
}

// ---- PDL controls ----
__device__ __forceinline__ void gdc_wait() {
    asm volatile("griddepcontrol.wait;" ::: "memory");
}
__device__ __forceinline__ void gdc_launch() {
    asm volatile("griddepcontrol.launch_dependents;");
}

// ---------------------------------------------------------------------------
// zero ONLY the degree array (acc zeroing folded into k_prep / k_node2)
__global__ __launch_bounds__(256) void k_zero() {
    int i = blockIdx.x * blockDim.x + threadIdx.x;
    if (i < NN) g_deg[i] = 0;
    gdc_launch();
}

// degree count over target (col) indices; 4 edges per thread
__global__ __launch_bounds__(256) void k_deg(const int* __restrict__ col, int E) {
    int i = (blockIdx.x * blockDim.x + threadIdx.x) * 4;
    if (i + 3 < E) {
        // col is a pure input — safe to load before predecessor (k_zero) finishes
        int4 c = __ldcs(reinterpret_cast<const int4*>(col + i));
        gdc_wait();                       // g_deg must be zeroed
        red_add_u32(&g_deg[c.x]);
        red_add_u32(&g_deg[c.y]);
        red_add_u32(&g_deg[c.z]);
        red_add_u32(&g_deg[c.w]);
    } else {
        gdc_wait();
    }
    gdc_launch();
}

// dis = rsqrt(deg + 1 self-loop); u = dis * x; also zero acc1 for k_scat1
__global__ __launch_bounds__(256) void k_prep(const float* __restrict__ x) {
    int i = blockIdx.x * blockDim.x + threadIdx.x;
    float xv = (i < NN) ? x[i] : 0.0f;    // pure input, pre-wait
    gdc_wait();                            // g_deg finalized
    if (i < NN) {
        float d = rsqrtf((float)(g_deg[i] + 1));
        g_dis[i]  = d;
        g_u[i]    = d * xv;
        g_acc1[i] = 0.0f;
    }
    gdc_launch();
}

// scatter layer-1 messages: acc1[col] += u[row]; 4 edges per thread
__global__ __launch_bounds__(256) void k_scat1(const int* __restrict__ row,
                                               const int* __restrict__ col, int E) {
    int i = (blockIdx.x * blockDim.x + threadIdx.x) * 4;
    if (i + 3 < E) {
        int4 r = __ldcs(reinterpret_cast<const int4*>(row + i));  // pure inputs
        int4 c = __ldcs(reinterpret_cast<const int4*>(col + i));
        gdc_wait();                       // g_u / g_acc1 ready
        float u0 = __ldg(&g_u[r.x]);
        float u1 = __ldg(&g_u[r.y]);
        float u2 = __ldg(&g_u[r.z]);
        float u3 = __ldg(&g_u[r.w]);
        red_add_f32(&g_acc1[c.x], u0);
        red_add_f32(&g_acc1[c.y], u1);
        red_add_f32(&g_acc1[c.z], u2);
        red_add_f32(&g_acc1[c.w], u3);
    } else {
        gdc_wait();
    }
    gdc_launch();
}

// per-node MLP: s -> relu(W1*s+b1) -> @W2 ; t = dis * g; also zero acc2
__global__ __launch_bounds__(256) void k_node2(const float4* __restrict__ W1,
                                               const float4* __restrict__ b1,
                                               const float4* __restrict__ W2) {
    int i = blockIdx.x * blockDim.x + threadIdx.x;
    // weights are pure inputs — load pre-wait
    float4 w1q[4], bbq[4], e0q[4], e1q[4];
#pragma unroll
    for (int q = 0; q < 4; q++) {
        w1q[q] = __ldg(&W1[q]);
        bbq[q] = __ldg(&b1[q]);
        e0q[q] = __ldg(&W2[2 * q]);
        e1q[q] = __ldg(&W2[2 * q + 1]);
    }
    gdc_wait();                            // g_acc1 finalized
    if (i < NN) {
        float d = g_dis[i];
        float s = d * (g_acc1[i] + g_u[i]);
        float g0 = 0.0f, g1 = 0.0f;
#pragma unroll
        for (int q = 0; q < 4; q++) {
            float h0 = fmaxf(fmaf(s, w1q[q].x, bbq[q].x), 0.0f);
            float h1 = fmaxf(fmaf(s, w1q[q].y, bbq[q].y), 0.0f);
            float h2 = fmaxf(fmaf(s, w1q[q].z, bbq[q].z), 0.0f);
            float h3 = fmaxf(fmaf(s, w1q[q].w, bbq[q].w), 0.0f);
            g0 = fmaf(h0, e0q[q].x, g0); g1 = fmaf(h0, e0q[q].y, g1);
            g0 = fmaf(h1, e0q[q].z, g0); g1 = fmaf(h1, e0q[q].w, g1);
            g0 = fmaf(h2, e1q[q].x, g0); g1 = fmaf(h2, e1q[q].y, g1);
            g0 = fmaf(h3, e1q[q].z, g0); g1 = fmaf(h3, e1q[q].w, g1);
        }
        g_t[i]    = make_float2(d * g0, d * g1);
        g_acc2[i] = make_float2(0.0f, 0.0f);
    }
    gdc_launch();
}

// scatter layer-2 messages: acc2[col] += t[row]; 4 edges per thread
__global__ __launch_bounds__(256) void k_scat2(const int* __restrict__ row,
                                               const int* __restrict__ col, int E) {
    int i = (blockIdx.x * blockDim.x + threadIdx.x) * 4;
    if (i + 3 < E) {
        int4 r = __ldcs(reinterpret_cast<const int4*>(row + i));  // pure inputs
        int4 c = __ldcs(reinterpret_cast<const int4*>(col + i));
        gdc_wait();                       // g_t / g_acc2 ready
        float2 t0 = __ldg(&g_t[r.x]);
        float2 t1 = __ldg(&g_t[r.y]);
        float2 t2 = __ldg(&g_t[r.z]);
        float2 t3 = __ldg(&g_t[r.w]);
        red_add_v2(&g_acc2[c.x], t0);
        red_add_v2(&g_acc2[c.y], t1);
        red_add_v2(&g_acc2[c.z], t2);
        red_add_v2(&g_acc2[c.w], t3);
    } else {
        gdc_wait();
    }
    gdc_launch();
}

// final: out = dis*(acc2 + t) + b2, then log_softmax over 2 classes
__global__ __launch_bounds__(256) void k_out(const float* __restrict__ b2,
                                             float2* __restrict__ out) {
    int i = blockIdx.x * blockDim.x + threadIdx.x;
    float b20 = __ldg(&b2[0]);            // pure inputs
    float b21 = __ldg(&b2[1]);
    gdc_wait();                            // g_acc2 finalized
    if (i < NN) {
        float d  = g_dis[i];
        float2 a = g_acc2[i];
        float2 t = g_t[i];
        float o0 = fmaf(d, a.x + t.x, b20);
        float o1 = fmaf(d, a.y + t.y, b21);
        float m  = fmaxf(o0, o1);
        float lse = m + log1pf(__expf(fminf(o0, o1) - m));
        out[i] = make_float2(o0 - lse, o1 - lse);
    }
}

// ---------------------------------------------------------------------------
static inline void launch_pdl(const void* func, int grid, int block, void** args) {
    cudaLaunchConfig_t cfg = {};
    cfg.gridDim = dim3(grid, 1, 1);
    cfg.blockDim = dim3(block, 1, 1);
    cfg.dynamicSmemBytes = 0;
    cfg.stream = 0;
    cudaLaunchAttribute attr[1];
    attr[0].id = cudaLaunchAttributeProgrammaticStreamSerialization;
    attr[0].val.programmaticStreamSerializationAllowed = 1;
    cfg.attrs = attr;
    cfg.numAttrs = 1;
    cudaLaunchKernelExC(&cfg, func, args);
}

extern "C" void kernel_launch(void* const* d_in, const int* in_sizes, int n_in,
                              void* d_out, int out_size) {
    const float* x   = (const float*)d_in[0];
    const int*   ei  = (const int*)d_in[1];
    const float* W1  = (const float*)d_in[2];
    const float* b1  = (const float*)d_in[3];
    const float* W2  = (const float*)d_in[4];
    const float* b2  = (const float*)d_in[5];
    float2* out = (float2*)d_out;

    const int E = in_sizes[1] / 2;      // edge_index is [2, E]
    const int* row = ei;                // source
    const int* col = ei + E;            // target

    const int TB = 256;
    const int nodeBlocks = (NN + TB - 1) / TB;
    const int edgeBlocks = (E / 4 + TB - 1) / TB;   // 4 edges per thread

    {   // k_zero
        void* args[] = {};
        launch_pdl((const void*)k_zero, nodeBlocks, TB, args);
    }
    {   // k_deg(col, E)
        void* a0 = (void*)col; int e = E;
        void* args[] = {&a0, &e};
        launch_pdl((const void*)k_deg, edgeBlocks, TB, args);
    }
    {   // k_prep(x)
        void* a0 = (void*)x;
        void* args[] = {&a0};
        launch_pdl((const void*)k_prep, nodeBlocks, TB, args);
    }
    {   // k_scat1(row, col, E)
        void* a0 = (void*)row; void* a1 = (void*)col; int e = E;
        void* args[] = {&a0, &a1, &e};
        launch_pdl((const void*)k_scat1, edgeBlocks, TB, args);
    }
    {   // k_node2(W1, b1, W2)
        void* a0 = (void*)W1; void* a1 = (void*)b1; void* a2 = (void*)W2;
        void* args[] = {&a0, &a1, &a2};
        launch_pdl((const void*)k_node2, nodeBlocks, TB, args);
    }
    {   // k_scat2(row, col, E)
        void* a0 = (void*)row; void* a1 = (void*)col; int e = E;
        void* args[] = {&a0, &a1, &e};
        launch_pdl((const void*)k_scat2, edgeBlocks, TB, args);
    }
    {   // k_out(b2, out)
        void* a0 = (void*)b2; void* a1 = (void*)out;
        void* args[] = {&a0, &a1};
        launch_pdl((const void*)k_out, nodeBlocks, TB, args);
    }
}